// round 1
// baseline (speedup 1.0000x reference)
#include <cuda_runtime.h>

#define NT 300000
#define NU 300000
#define ND 100000
#define EDG 2000000

// ---------------- scratch (static device memory; no allocations) ----------------
__device__ int g_cnt_u2t[NT];
__device__ int g_cnt_d2t[NT];
__device__ int g_cnt_t2u[NU];
__device__ int g_cnt_t2d[ND];
__device__ int g_off_u2t[NT + 1];
__device__ int g_off_d2t[NT + 1];
__device__ int g_off_t2u[NU + 1];
__device__ int g_off_t2d[ND + 1];
__device__ int g_cur_u2t[NT];
__device__ int g_cur_d2t[NT];
__device__ int g_cur_t2u[NU];
__device__ int g_cur_t2d[ND];
__device__ int g_ss_u2t[EDG];
__device__ int g_ss_d2t[EDG];
__device__ int g_ss_t2u[EDG];
__device__ int g_ss_t2d[EDG];
__device__ float g_wh_u2t[NU * 64];
__device__ float g_wh_t2u[NT * 64];
__device__ float g_wh_d2t[ND * 64];
__device__ float g_wh_t2d[NT * 64];
__device__ float g_agg_t[NT * 64];
__device__ float g_agg_u[NU * 64];
__device__ float g_agg_d[ND * 64];

// ---------------- zero the degree counters ----------------
__global__ void k_zero() {
    int i = blockIdx.x * blockDim.x + threadIdx.x;
    if (i < NT) { g_cnt_u2t[i] = 0; g_cnt_d2t[i] = 0; }
    if (i < NU) g_cnt_t2u[i] = 0;
    if (i < ND) g_cnt_t2d[i] = 0;
}

// ---------------- degree histogram ----------------
__global__ void k_hist(const int* __restrict__ dst, int* __restrict__ cnt) {
    int i = blockIdx.x * blockDim.x + threadIdx.x;
    if (i < EDG) atomicAdd(&cnt[dst[i]], 1);
}

// ---------------- exclusive scan of the 4 count arrays (one block each) ----------------
__global__ void k_scan() {
    int rel = blockIdx.x;
    const int* cnt; int* off; int* cur; int n;
    if (rel == 0)      { cnt = g_cnt_u2t; off = g_off_u2t; cur = g_cur_u2t; n = NT; }
    else if (rel == 1) { cnt = g_cnt_d2t; off = g_off_d2t; cur = g_cur_d2t; n = NT; }
    else if (rel == 2) { cnt = g_cnt_t2u; off = g_off_t2u; cur = g_cur_t2u; n = NU; }
    else               { cnt = g_cnt_t2d; off = g_off_t2d; cur = g_cur_t2d; n = ND; }

    __shared__ int wsum[32];
    __shared__ int s_run;
    int tid = threadIdx.x, lane = tid & 31, wid = tid >> 5;
    if (tid == 0) s_run = 0;
    __syncthreads();

    for (int base = 0; base < n; base += 1024) {
        int i = base + tid;
        int v = (i < n) ? cnt[i] : 0;
        int x = v;
        #pragma unroll
        for (int d = 1; d < 32; d <<= 1) {
            int t = __shfl_up_sync(0xffffffffu, x, d);
            if (lane >= d) x += t;
        }
        if (lane == 31) wsum[wid] = x;
        __syncthreads();
        if (wid == 0) {
            int w = wsum[lane];
            #pragma unroll
            for (int d = 1; d < 32; d <<= 1) {
                int t = __shfl_up_sync(0xffffffffu, w, d);
                if (lane >= d) w += t;
            }
            wsum[lane] = w;
        }
        __syncthreads();
        int warpoff = (wid > 0) ? wsum[wid - 1] : 0;
        int incl = x + warpoff;
        int run = s_run;
        if (i < n) { int ex = run + incl - v; off[i] = ex; cur[i] = ex; }
        __syncthreads();
        if (tid == 1023) s_run = run + incl;
        __syncthreads();
    }
    if (tid == 0) off[n] = s_run;
}

// ---------------- CSR fill: bucket src ids by dst ----------------
__global__ void k_fill(const int* __restrict__ src, const int* __restrict__ dst,
                       int* __restrict__ cur, int* __restrict__ ss) {
    int i = blockIdx.x * blockDim.x + threadIdx.x;
    if (i < EDG) {
        int d = dst[i];
        int p = atomicAdd(&cur[d], 1);
        ss[p] = src[i];
    }
}

// ---------------- GEMM: out = act(H) @ W + b,  H: n x 64, W: 64 x 64 ----------------
template <bool ACT>
__global__ __launch_bounds__(256) void k_gemm(const float* __restrict__ H,
                                              const float* __restrict__ W,
                                              const float* __restrict__ bias,
                                              float* __restrict__ out, int n) {
    __shared__ __align__(16) float Ws[64 * 64];
    __shared__ float As[64 * 65];
    int tid = threadIdx.x;

    const float4* W4 = (const float4*)W;
    float4* Ws4 = (float4*)Ws;
    #pragma unroll
    for (int q = 0; q < 4; q++) Ws4[tid + q * 256] = W4[tid + q * 256];

    int row0 = blockIdx.x * 64;
    const float4* H4 = (const float4*)H;
    #pragma unroll
    for (int q = 0; q < 4; q++) {
        int fidx = tid + q * 256;
        int r = fidx >> 4, c4 = fidx & 15;
        int gr = row0 + r;
        float4 v = make_float4(0.f, 0.f, 0.f, 0.f);
        if (gr < n) v = H4[(long)gr * 16 + c4];
        if (ACT) {
            v.x = v.x > 0.f ? v.x : 0.01f * v.x;
            v.y = v.y > 0.f ? v.y : 0.01f * v.y;
            v.z = v.z > 0.f ? v.z : 0.01f * v.z;
            v.w = v.w > 0.f ? v.w : 0.01f * v.w;
        }
        float* a = &As[r * 65 + c4 * 4];
        a[0] = v.x; a[1] = v.y; a[2] = v.z; a[3] = v.w;
    }
    __syncthreads();

    int r = tid >> 2, cg = tid & 3;
    float acc[16];
    #pragma unroll
    for (int j = 0; j < 16; j++) acc[j] = __ldg(&bias[cg * 16 + j]);

    const float* ap = &As[r * 65];
    #pragma unroll
    for (int k = 0; k < 64; k++) {
        float a = ap[k];
        const float4* wrow = (const float4*)&Ws[k * 64 + cg * 16];
        float4 w0 = wrow[0], w1 = wrow[1], w2 = wrow[2], w3 = wrow[3];
        acc[0]  += a * w0.x; acc[1]  += a * w0.y; acc[2]  += a * w0.z; acc[3]  += a * w0.w;
        acc[4]  += a * w1.x; acc[5]  += a * w1.y; acc[6]  += a * w1.z; acc[7]  += a * w1.w;
        acc[8]  += a * w2.x; acc[9]  += a * w2.y; acc[10] += a * w2.z; acc[11] += a * w2.w;
        acc[12] += a * w3.x; acc[13] += a * w3.y; acc[14] += a * w3.z; acc[15] += a * w3.w;
    }

    int gr = row0 + r;
    if (gr < n) {
        float4* o = (float4*)&out[(long)gr * 64 + cg * 16];
        o[0] = make_float4(acc[0],  acc[1],  acc[2],  acc[3]);
        o[1] = make_float4(acc[4],  acc[5],  acc[6],  acc[7]);
        o[2] = make_float4(acc[8],  acc[9],  acc[10], acc[11]);
        o[3] = make_float4(acc[12], acc[13], acc[14], acc[15]);
    }
}

// ---------------- single-relation segment-mean gather (dst-side, no atomics) ----------------
__global__ void k_gather1(const float* __restrict__ wh, const int* __restrict__ off,
                          const int* __restrict__ ss, float* __restrict__ outp, int n) {
    int t = blockIdx.x * blockDim.x + threadIdx.x;
    int node = t >> 4, j = t & 15;
    if (node >= n) return;
    int s0 = off[node], e0 = off[node + 1];
    float4 acc = make_float4(0.f, 0.f, 0.f, 0.f);
    for (int k = s0; k < e0; k++) {
        int s = __ldg(&ss[k]);
        float4 v = __ldg((const float4*)&wh[(long)s * 64 + j * 4]);
        acc.x += v.x; acc.y += v.y; acc.z += v.z; acc.w += v.w;
    }
    int d = e0 - s0;
    float inv = 1.0f / (float)(d > 0 ? d : 1);
    float4 o = make_float4(acc.x * inv, acc.y * inv, acc.z * inv, acc.w * inv);
    *(float4*)&outp[(long)node * 64 + j * 4] = o;
}

// ---------------- two-relation gather for target nodes: mean(u2t) + mean(d2t) ----------------
__global__ void k_gather_t(const float* __restrict__ whA, const int* __restrict__ offA,
                           const int* __restrict__ ssA,
                           const float* __restrict__ whB, const int* __restrict__ offB,
                           const int* __restrict__ ssB,
                           float* __restrict__ outp) {
    int t = blockIdx.x * blockDim.x + threadIdx.x;
    int node = t >> 4, j = t & 15;
    if (node >= NT) return;

    float4 a1 = make_float4(0.f, 0.f, 0.f, 0.f);
    int s0 = offA[node], e0 = offA[node + 1];
    for (int k = s0; k < e0; k++) {
        int s = __ldg(&ssA[k]);
        float4 v = __ldg((const float4*)&whA[(long)s * 64 + j * 4]);
        a1.x += v.x; a1.y += v.y; a1.z += v.z; a1.w += v.w;
    }
    int d1 = e0 - s0;
    float i1 = 1.0f / (float)(d1 > 0 ? d1 : 1);

    float4 a2 = make_float4(0.f, 0.f, 0.f, 0.f);
    int s1 = offB[node], e1 = offB[node + 1];
    for (int k = s1; k < e1; k++) {
        int s = __ldg(&ssB[k]);
        float4 v = __ldg((const float4*)&whB[(long)s * 64 + j * 4]);
        a2.x += v.x; a2.y += v.y; a2.z += v.z; a2.w += v.w;
    }
    int d2 = e1 - s1;
    float i2 = 1.0f / (float)(d2 > 0 ? d2 : 1);

    float4 o = make_float4(a1.x * i1 + a2.x * i2, a1.y * i1 + a2.y * i2,
                           a1.z * i1 + a2.z * i2, a1.w * i1 + a2.w * i2);
    *(float4*)&outp[(long)node * 64 + j * 4] = o;
}

// ---------------- classifier: out[i,:] = agg_t[i,:] @ Wc + bc,  Wc: 64 x 2 ----------------
__global__ void k_cls(const float* __restrict__ Wc, const float* __restrict__ bc,
                      float* __restrict__ out) {
    int t = blockIdx.x * blockDim.x + threadIdx.x;
    int node = t >> 4, j = t & 15;
    if (node >= NT) return;
    float4 a = *(const float4*)&g_agg_t[(long)node * 64 + j * 4];
    int c0 = j * 4;
    float p0 = a.x * __ldg(&Wc[(c0 + 0) * 2]) + a.y * __ldg(&Wc[(c0 + 1) * 2]) +
               a.z * __ldg(&Wc[(c0 + 2) * 2]) + a.w * __ldg(&Wc[(c0 + 3) * 2]);
    float p1 = a.x * __ldg(&Wc[(c0 + 0) * 2 + 1]) + a.y * __ldg(&Wc[(c0 + 1) * 2 + 1]) +
               a.z * __ldg(&Wc[(c0 + 2) * 2 + 1]) + a.w * __ldg(&Wc[(c0 + 3) * 2 + 1]);
    #pragma unroll
    for (int o = 8; o > 0; o >>= 1) {
        p0 += __shfl_down_sync(0xffffffffu, p0, o, 16);
        p1 += __shfl_down_sync(0xffffffffu, p1, o, 16);
    }
    if (j == 0) {
        out[(long)node * 2 + 0] = p0 + __ldg(&bc[0]);
        out[(long)node * 2 + 1] = p1 + __ldg(&bc[1]);
    }
}

static void* symaddr(const void* sym) {
    void* p = nullptr;
    cudaGetSymbolAddress(&p, sym);
    return p;
}

extern "C" void kernel_launch(void* const* d_in, const int* in_sizes, int n_in,
                              void* d_out, int out_size) {
    const float* features   = (const float*)d_in[0];
    const float* emb_user   = (const float*)d_in[1];
    const float* emb_device = (const float*)d_in[2];
    const float* W0 = (const float*)d_in[3];
    const float* b0 = (const float*)d_in[4];
    const float* W1 = (const float*)d_in[5];
    const float* b1 = (const float*)d_in[6];
    const float* Wc = (const float*)d_in[7];
    const float* bc = (const float*)d_in[8];
    const int* src_u2t = (const int*)d_in[9];
    const int* dst_u2t = (const int*)d_in[10];
    const int* src_t2u = (const int*)d_in[11];
    const int* dst_t2u = (const int*)d_in[12];
    const int* src_d2t = (const int*)d_in[13];
    const int* dst_d2t = (const int*)d_in[14];
    const int* src_t2d = (const int*)d_in[15];
    const int* dst_t2d = (const int*)d_in[16];
    float* out = (float*)d_out;

    int* cnt_u2t = (int*)symaddr(g_cnt_u2t);
    int* cnt_d2t = (int*)symaddr(g_cnt_d2t);
    int* cnt_t2u = (int*)symaddr(g_cnt_t2u);
    int* cnt_t2d = (int*)symaddr(g_cnt_t2d);
    int* off_u2t = (int*)symaddr(g_off_u2t);
    int* off_d2t = (int*)symaddr(g_off_d2t);
    int* off_t2u = (int*)symaddr(g_off_t2u);
    int* off_t2d = (int*)symaddr(g_off_t2d);
    int* cur_u2t = (int*)symaddr(g_cur_u2t);
    int* cur_d2t = (int*)symaddr(g_cur_d2t);
    int* cur_t2u = (int*)symaddr(g_cur_t2u);
    int* cur_t2d = (int*)symaddr(g_cur_t2d);
    int* ss_u2t  = (int*)symaddr(g_ss_u2t);
    int* ss_d2t  = (int*)symaddr(g_ss_d2t);
    int* ss_t2u  = (int*)symaddr(g_ss_t2u);
    int* ss_t2d  = (int*)symaddr(g_ss_t2d);
    float* wh_u2t = (float*)symaddr(g_wh_u2t);
    float* wh_t2u = (float*)symaddr(g_wh_t2u);
    float* wh_d2t = (float*)symaddr(g_wh_d2t);
    float* wh_t2d = (float*)symaddr(g_wh_t2d);
    float* agg_t  = (float*)symaddr(g_agg_t);
    float* agg_u  = (float*)symaddr(g_agg_u);
    float* agg_d  = (float*)symaddr(g_agg_d);

    const int TPB = 256;
    int egrid = (EDG + TPB - 1) / TPB;

    // ---- CSR build (shared across both layers) ----
    k_zero<<<(NT + TPB - 1) / TPB, TPB>>>();
    k_hist<<<egrid, TPB>>>(dst_u2t, cnt_u2t);
    k_hist<<<egrid, TPB>>>(dst_d2t, cnt_d2t);
    k_hist<<<egrid, TPB>>>(dst_t2u, cnt_t2u);
    k_hist<<<egrid, TPB>>>(dst_t2d, cnt_t2d);
    k_scan<<<4, 1024>>>();
    k_fill<<<egrid, TPB>>>(src_u2t, dst_u2t, cur_u2t, ss_u2t);
    k_fill<<<egrid, TPB>>>(src_d2t, dst_d2t, cur_d2t, ss_d2t);
    k_fill<<<egrid, TPB>>>(src_t2u, dst_t2u, cur_t2u, ss_t2u);
    k_fill<<<egrid, TPB>>>(src_t2d, dst_t2d, cur_t2d, ss_t2d);

    // ---- layer 0: 4 projections + 3 aggregations ----
    k_gemm<false><<<(NU + 63) / 64, TPB>>>(emb_user,   W0 + 0 * 4096, b0 + 0,   wh_u2t, NU);
    k_gemm<false><<<(NT + 63) / 64, TPB>>>(features,   W0 + 1 * 4096, b0 + 64,  wh_t2u, NT);
    k_gemm<false><<<(ND + 63) / 64, TPB>>>(emb_device, W0 + 2 * 4096, b0 + 128, wh_d2t, ND);
    k_gemm<false><<<(NT + 63) / 64, TPB>>>(features,   W0 + 3 * 4096, b0 + 192, wh_t2d, NT);
    k_gather_t<<<(NT * 16 + TPB - 1) / TPB, TPB>>>(wh_u2t, off_u2t, ss_u2t,
                                                   wh_d2t, off_d2t, ss_d2t, agg_t);
    k_gather1<<<(NU * 16 + TPB - 1) / TPB, TPB>>>(wh_t2u, off_t2u, ss_t2u, agg_u, NU);
    k_gather1<<<(ND * 16 + TPB - 1) / TPB, TPB>>>(wh_t2d, off_t2d, ss_t2d, agg_d, ND);

    // ---- layer 1: only h_t is needed downstream -> only u2t and d2t branches ----
    k_gemm<true><<<(NU + 63) / 64, TPB>>>(agg_u, W1 + 0 * 4096, b1 + 0,   wh_u2t, NU);
    k_gemm<true><<<(ND + 63) / 64, TPB>>>(agg_d, W1 + 2 * 4096, b1 + 128, wh_d2t, ND);
    k_gather_t<<<(NT * 16 + TPB - 1) / TPB, TPB>>>(wh_u2t, off_u2t, ss_u2t,
                                                   wh_d2t, off_d2t, ss_d2t, agg_t);

    // ---- classifier ----
    k_cls<<<(NT * 16 + TPB - 1) / TPB, TPB>>>(Wc, bc, out);
}

// round 2
// speedup vs baseline: 2.1242x; 2.1242x over previous
#include <cuda_runtime.h>

#define NT 300000
#define NU 300000
#define ND 100000
#define EDG 2000000

// ---------------- scratch (static device memory; no allocations) ----------------
__device__ int g_cnt_u2t[NT];
__device__ int g_cnt_d2t[NT];
__device__ int g_cnt_t2u[NU];
__device__ int g_cnt_t2d[ND];
__device__ int g_off_u2t[NT + 1];
__device__ int g_off_d2t[NT + 1];
__device__ int g_off_t2u[NU + 1];
__device__ int g_off_t2d[ND + 1];
__device__ int g_cur_u2t[NT];
__device__ int g_cur_d2t[NT];
__device__ int g_cur_t2u[NU];
__device__ int g_cur_t2d[ND];
__device__ int g_ss_u2t[EDG];
__device__ int g_ss_d2t[EDG];
__device__ int g_ss_t2u[EDG];
__device__ int g_ss_t2d[EDG];
__device__ float g_wh_t2u[(size_t)NT * 64];
__device__ float g_wh_t2d[(size_t)NT * 64];
__device__ float g_p_u[(size_t)NU * 2];
__device__ float g_p_d[(size_t)ND * 2];
__device__ float g_w1c[2][128];   // [rel][c*2+o] : W1[{0,2}] @ Wc
__device__ float g_b1c[2][2];     // [rel][o]     : b1[{0,2}] @ Wc

// ---------------- zero the degree counters ----------------
__global__ void k_zero() {
    int i = blockIdx.x * blockDim.x + threadIdx.x;
    if (i < NT) { g_cnt_u2t[i] = 0; g_cnt_d2t[i] = 0; }
    if (i < NU) g_cnt_t2u[i] = 0;
    if (i < ND) g_cnt_t2d[i] = 0;
}

// ---------------- fused degree histogram over all 4 relations ----------------
__global__ void k_hist4(const int* __restrict__ d0, const int* __restrict__ d1,
                        const int* __restrict__ d2, const int* __restrict__ d3) {
    int i = blockIdx.x * blockDim.x + threadIdx.x;
    if (i < EDG)               atomicAdd(&g_cnt_u2t[d0[i]], 1);
    else if (i < 2 * EDG)      atomicAdd(&g_cnt_d2t[d1[i - EDG]], 1);
    else if (i < 3 * EDG)      atomicAdd(&g_cnt_t2u[d2[i - 2 * EDG]], 1);
    else if (i < 4 * EDG)      atomicAdd(&g_cnt_t2d[d3[i - 3 * EDG]], 1);
}

// ---------------- exclusive scan of the 4 count arrays (one block each) ----------------
__global__ void k_scan() {
    int rel = blockIdx.x;
    const int* cnt; int* off; int* cur; int n;
    if (rel == 0)      { cnt = g_cnt_u2t; off = g_off_u2t; cur = g_cur_u2t; n = NT; }
    else if (rel == 1) { cnt = g_cnt_d2t; off = g_off_d2t; cur = g_cur_d2t; n = NT; }
    else if (rel == 2) { cnt = g_cnt_t2u; off = g_off_t2u; cur = g_cur_t2u; n = NU; }
    else               { cnt = g_cnt_t2d; off = g_off_t2d; cur = g_cur_t2d; n = ND; }

    __shared__ int wsum[32];
    __shared__ int s_run;
    int tid = threadIdx.x, lane = tid & 31, wid = tid >> 5;
    if (tid == 0) s_run = 0;
    __syncthreads();

    for (int base = 0; base < n; base += 1024) {
        int i = base + tid;
        int v = (i < n) ? cnt[i] : 0;
        int x = v;
        #pragma unroll
        for (int d = 1; d < 32; d <<= 1) {
            int t = __shfl_up_sync(0xffffffffu, x, d);
            if (lane >= d) x += t;
        }
        if (lane == 31) wsum[wid] = x;
        __syncthreads();
        if (wid == 0) {
            int w = wsum[lane];
            #pragma unroll
            for (int d = 1; d < 32; d <<= 1) {
                int t = __shfl_up_sync(0xffffffffu, w, d);
                if (lane >= d) w += t;
            }
            wsum[lane] = w;
        }
        __syncthreads();
        int warpoff = (wid > 0) ? wsum[wid - 1] : 0;
        int incl = x + warpoff;
        int run = s_run;
        if (i < n) { int ex = run + incl - v; off[i] = ex; cur[i] = ex; }
        __syncthreads();
        if (tid == 1023) s_run = run + incl;
        __syncthreads();
    }
    if (tid == 0) off[n] = s_run;
}

// ---------------- fused CSR fill over all 4 relations ----------------
__global__ void k_fill4(const int* __restrict__ s0, const int* __restrict__ d0,
                        const int* __restrict__ s1, const int* __restrict__ d1,
                        const int* __restrict__ s2, const int* __restrict__ d2,
                        const int* __restrict__ s3, const int* __restrict__ d3) {
    int i = blockIdx.x * blockDim.x + threadIdx.x;
    if (i < EDG) {
        int p = atomicAdd(&g_cur_u2t[d0[i]], 1);
        g_ss_u2t[p] = s0[i];
    } else if (i < 2 * EDG) {
        int e = i - EDG;
        int p = atomicAdd(&g_cur_d2t[d1[e]], 1);
        g_ss_d2t[p] = s1[e];
    } else if (i < 3 * EDG) {
        int e = i - 2 * EDG;
        int p = atomicAdd(&g_cur_t2u[d2[e]], 1);
        g_ss_t2u[p] = s2[e];
    } else if (i < 4 * EDG) {
        int e = i - 3 * EDG;
        int p = atomicAdd(&g_cur_t2d[d3[e]], 1);
        g_ss_t2d[p] = s3[e];
    }
}

// ---------------- fold classifier into layer-1 weights: W1c = W1[rel]@Wc ----------------
__global__ void k_foldw(const float* __restrict__ W1, const float* __restrict__ b1,
                        const float* __restrict__ Wc) {
    int t = threadIdx.x;             // 256 threads
    int rel = t >> 7;                // 0 -> W1[0] (u path), 1 -> W1[2] (d path)
    int idx = t & 127;
    int c = idx >> 1, o = idx & 1;
    const float* Wsrc = W1 + (rel == 0 ? 0 : 2) * 4096;
    float s = 0.f;
    #pragma unroll 8
    for (int k = 0; k < 64; k++) s += Wsrc[c * 64 + k] * Wc[k * 2 + o];
    g_w1c[rel][idx] = s;
    if (t < 4) {
        int r2 = t >> 1, o2 = t & 1;
        const float* bsrc = b1 + (r2 == 0 ? 0 : 2) * 64;
        float sb = 0.f;
        #pragma unroll 8
        for (int k = 0; k < 64; k++) sb += bsrc[k] * Wc[k * 2 + o2];
        g_b1c[r2][o2] = sb;
    }
}

// ---------------- GEMM: out = H @ W + b,  H: n x 64, W: 64 x 64 ----------------
__global__ __launch_bounds__(256) void k_gemm(const float* __restrict__ H,
                                              const float* __restrict__ W,
                                              const float* __restrict__ bias,
                                              float* __restrict__ out, int n) {
    __shared__ __align__(16) float Ws[64 * 64];
    __shared__ float As[64 * 65];
    int tid = threadIdx.x;

    const float4* W4 = (const float4*)W;
    float4* Ws4 = (float4*)Ws;
    #pragma unroll
    for (int q = 0; q < 4; q++) Ws4[tid + q * 256] = W4[tid + q * 256];

    int row0 = blockIdx.x * 64;
    const float4* H4 = (const float4*)H;
    #pragma unroll
    for (int q = 0; q < 4; q++) {
        int fidx = tid + q * 256;
        int r = fidx >> 4, c4 = fidx & 15;
        int gr = row0 + r;
        float4 v = make_float4(0.f, 0.f, 0.f, 0.f);
        if (gr < n) v = H4[(long)gr * 16 + c4];
        float* a = &As[r * 65 + c4 * 4];
        a[0] = v.x; a[1] = v.y; a[2] = v.z; a[3] = v.w;
    }
    __syncthreads();

    int r = tid >> 2, cg = tid & 3;
    float acc[16];
    #pragma unroll
    for (int j = 0; j < 16; j++) acc[j] = __ldg(&bias[cg * 16 + j]);

    const float* ap = &As[r * 65];
    #pragma unroll
    for (int k = 0; k < 64; k++) {
        float a = ap[k];
        const float4* wrow = (const float4*)&Ws[k * 64 + cg * 16];
        float4 w0 = wrow[0], w1 = wrow[1], w2 = wrow[2], w3 = wrow[3];
        acc[0]  += a * w0.x; acc[1]  += a * w0.y; acc[2]  += a * w0.z; acc[3]  += a * w0.w;
        acc[4]  += a * w1.x; acc[5]  += a * w1.y; acc[6]  += a * w1.z; acc[7]  += a * w1.w;
        acc[8]  += a * w2.x; acc[9]  += a * w2.y; acc[10] += a * w2.z; acc[11] += a * w2.w;
        acc[12] += a * w3.x; acc[13] += a * w3.y; acc[14] += a * w3.z; acc[15] += a * w3.w;
    }

    int gr = row0 + r;
    if (gr < n) {
        float4* o = (float4*)&out[(long)gr * 64 + cg * 16];
        o[0] = make_float4(acc[0],  acc[1],  acc[2],  acc[3]);
        o[1] = make_float4(acc[4],  acc[5],  acc[6],  acc[7]);
        o[2] = make_float4(acc[8],  acc[9],  acc[10], acc[11]);
        o[3] = make_float4(acc[12], acc[13], acc[14], acc[15]);
    }
}

// ---------- fused: mean-gather 64-dim -> leaky -> @W1c (64x2) + b1c -> p (n x 2) ----------
// 16 threads per node, each owning a float4 feature chunk; unroll-4 for MLP.
__global__ __launch_bounds__(256) void k_gather_proj(const float* __restrict__ wh,
                                                     const int* __restrict__ off,
                                                     const int* __restrict__ ss,
                                                     int rel,
                                                     float* __restrict__ p, int n) {
    __shared__ float sw[128];
    __shared__ float sb[2];
    if (threadIdx.x < 128) sw[threadIdx.x] = g_w1c[rel][threadIdx.x];
    if (threadIdx.x < 2)   sb[threadIdx.x] = g_b1c[rel][threadIdx.x];
    __syncthreads();

    int t = blockIdx.x * blockDim.x + threadIdx.x;
    int node = t >> 4, j = t & 15;
    // grids are sized so node < n always (n*16 divisible by 256)

    int s0 = off[node], e0 = off[node + 1];
    const float4* wh4 = (const float4*)wh;
    float4 acc = make_float4(0.f, 0.f, 0.f, 0.f);
    int k = s0;
    for (; k + 4 <= e0; k += 4) {
        int i0 = __ldg(&ss[k]);
        int i1 = __ldg(&ss[k + 1]);
        int i2 = __ldg(&ss[k + 2]);
        int i3 = __ldg(&ss[k + 3]);
        float4 v0 = __ldg(&wh4[(long)i0 * 16 + j]);
        float4 v1 = __ldg(&wh4[(long)i1 * 16 + j]);
        float4 v2 = __ldg(&wh4[(long)i2 * 16 + j]);
        float4 v3 = __ldg(&wh4[(long)i3 * 16 + j]);
        acc.x += (v0.x + v1.x) + (v2.x + v3.x);
        acc.y += (v0.y + v1.y) + (v2.y + v3.y);
        acc.z += (v0.z + v1.z) + (v2.z + v3.z);
        acc.w += (v0.w + v1.w) + (v2.w + v3.w);
    }
    for (; k < e0; k++) {
        int s = __ldg(&ss[k]);
        float4 v = __ldg(&wh4[(long)s * 16 + j]);
        acc.x += v.x; acc.y += v.y; acc.z += v.z; acc.w += v.w;
    }
    int d = e0 - s0;
    float inv = 1.0f / (float)(d > 0 ? d : 1);
    float m0 = acc.x * inv, m1 = acc.y * inv, m2 = acc.z * inv, m3 = acc.w * inv;
    // leaky relu (slope 0.01)
    m0 = m0 > 0.f ? m0 : 0.01f * m0;
    m1 = m1 > 0.f ? m1 : 0.01f * m1;
    m2 = m2 > 0.f ? m2 : 0.01f * m2;
    m3 = m3 > 0.f ? m3 : 0.01f * m3;

    int c0 = j * 4;
    float p0 = m0 * sw[(c0 + 0) * 2] + m1 * sw[(c0 + 1) * 2] +
               m2 * sw[(c0 + 2) * 2] + m3 * sw[(c0 + 3) * 2];
    float p1 = m0 * sw[(c0 + 0) * 2 + 1] + m1 * sw[(c0 + 1) * 2 + 1] +
               m2 * sw[(c0 + 2) * 2 + 1] + m3 * sw[(c0 + 3) * 2 + 1];
    #pragma unroll
    for (int o = 8; o > 0; o >>= 1) {
        p0 += __shfl_down_sync(0xffffffffu, p0, o, 16);
        p1 += __shfl_down_sync(0xffffffffu, p1, o, 16);
    }
    if (j == 0) {
        p[(long)node * 2 + 0] = p0 + sb[0];
        p[(long)node * 2 + 1] = p1 + sb[1];
    }
}

// ---------- final: out[t,:] = mean(p_u[src_u2t]) + mean(p_d[src_d2t]) + bc ----------
__global__ void k_final(const float* __restrict__ bc, float* __restrict__ out) {
    int node = blockIdx.x * blockDim.x + threadIdx.x;
    if (node >= NT) return;
    const float2* pu2 = (const float2*)g_p_u;
    const float2* pd2 = (const float2*)g_p_d;

    float a0 = 0.f, a1 = 0.f;
    {
        int s = g_off_u2t[node], e = g_off_u2t[node + 1];
        int k = s;
        for (; k + 4 <= e; k += 4) {
            int i0 = g_ss_u2t[k], i1 = g_ss_u2t[k + 1], i2 = g_ss_u2t[k + 2], i3 = g_ss_u2t[k + 3];
            float2 v0 = __ldg(&pu2[i0]), v1 = __ldg(&pu2[i1]);
            float2 v2 = __ldg(&pu2[i2]), v3 = __ldg(&pu2[i3]);
            a0 += (v0.x + v1.x) + (v2.x + v3.x);
            a1 += (v0.y + v1.y) + (v2.y + v3.y);
        }
        for (; k < e; k++) { float2 v = __ldg(&pu2[g_ss_u2t[k]]); a0 += v.x; a1 += v.y; }
        int d = e - s;
        float inv = 1.0f / (float)(d > 0 ? d : 1);
        a0 *= inv; a1 *= inv;
    }
    float b0a = 0.f, b1a = 0.f;
    {
        int s = g_off_d2t[node], e = g_off_d2t[node + 1];
        int k = s;
        for (; k + 4 <= e; k += 4) {
            int i0 = g_ss_d2t[k], i1 = g_ss_d2t[k + 1], i2 = g_ss_d2t[k + 2], i3 = g_ss_d2t[k + 3];
            float2 v0 = __ldg(&pd2[i0]), v1 = __ldg(&pd2[i1]);
            float2 v2 = __ldg(&pd2[i2]), v3 = __ldg(&pd2[i3]);
            b0a += (v0.x + v1.x) + (v2.x + v3.x);
            b1a += (v0.y + v1.y) + (v2.y + v3.y);
        }
        for (; k < e; k++) { float2 v = __ldg(&pd2[g_ss_d2t[k]]); b0a += v.x; b1a += v.y; }
        int d = e - s;
        float inv = 1.0f / (float)(d > 0 ? d : 1);
        b0a *= inv; b1a *= inv;
    }
    float2 o = make_float2(a0 + b0a + __ldg(&bc[0]), a1 + b1a + __ldg(&bc[1]));
    *(float2*)&out[(long)node * 2] = o;
}

static void* symaddr(const void* sym) {
    void* p = nullptr;
    cudaGetSymbolAddress(&p, sym);
    return p;
}

extern "C" void kernel_launch(void* const* d_in, const int* in_sizes, int n_in,
                              void* d_out, int out_size) {
    const float* features   = (const float*)d_in[0];
    const float* W0 = (const float*)d_in[3];
    const float* b0 = (const float*)d_in[4];
    const float* W1 = (const float*)d_in[5];
    const float* b1 = (const float*)d_in[6];
    const float* Wc = (const float*)d_in[7];
    const float* bc = (const float*)d_in[8];
    const int* src_u2t = (const int*)d_in[9];
    const int* dst_u2t = (const int*)d_in[10];
    const int* src_t2u = (const int*)d_in[11];
    const int* dst_t2u = (const int*)d_in[12];
    const int* src_d2t = (const int*)d_in[13];
    const int* dst_d2t = (const int*)d_in[14];
    const int* src_t2d = (const int*)d_in[15];
    const int* dst_t2d = (const int*)d_in[16];
    float* out = (float*)d_out;

    int* off_t2u = (int*)symaddr(g_off_t2u);
    int* off_t2d = (int*)symaddr(g_off_t2d);
    int* ss_t2u  = (int*)symaddr(g_ss_t2u);
    int* ss_t2d  = (int*)symaddr(g_ss_t2d);
    float* wh_t2u = (float*)symaddr(g_wh_t2u);
    float* wh_t2d = (float*)symaddr(g_wh_t2d);
    float* p_u = (float*)symaddr(g_p_u);
    float* p_d = (float*)symaddr(g_p_d);

    const int TPB = 256;
    int egrid4 = (4 * EDG + TPB - 1) / TPB;

    // ---- CSR build (all 4 relations) ----
    k_zero<<<(NT + TPB - 1) / TPB, TPB>>>();
    k_hist4<<<egrid4, TPB>>>(dst_u2t, dst_d2t, dst_t2u, dst_t2d);
    k_scan<<<4, 1024>>>();
    k_fill4<<<egrid4, TPB>>>(src_u2t, dst_u2t, src_d2t, dst_d2t,
                             src_t2u, dst_t2u, src_t2d, dst_t2d);

    // ---- fold classifier into layer-1 weights ----
    k_foldw<<<1, 256>>>(W1, b1, Wc);

    // ---- layer 0: only the two live projections (t2u, t2d) ----
    k_gemm<<<(NT + 63) / 64, TPB>>>(features, W0 + 1 * 4096, b0 + 64,  wh_t2u, NT);
    k_gemm<<<(NT + 63) / 64, TPB>>>(features, W0 + 3 * 4096, b0 + 192, wh_t2d, NT);

    // ---- fused gather + leaky + 2-wide layer-1 projection ----
    k_gather_proj<<<NU * 16 / TPB, TPB>>>(wh_t2u, off_t2u, ss_t2u, 0, p_u, NU);
    k_gather_proj<<<ND * 16 / TPB, TPB>>>(wh_t2d, off_t2d, ss_t2d, 1, p_d, ND);

    // ---- final 2-wide mean-gathers + bias ----
    k_final<<<(NT + TPB - 1) / TPB, TPB>>>(bc, out);
}

// round 3
// speedup vs baseline: 2.8062x; 1.3211x over previous
#include <cuda_runtime.h>
#include <cuda_fp16.h>

#define NT 300000
#define NU 300000
#define ND 100000
#define EDG 2000000
#define BU 293   // ceil(NU/1024)
#define BD 98    // ceil(ND/1024)

// ---------------- scratch (static device memory; no allocations) ----------------
__device__ int g_cnt_u2t[NT];
__device__ int g_cnt_d2t[NT];
__device__ int g_cnt_t2u[NU];
__device__ int g_cnt_t2d[ND];
__device__ int g_off_t2u[NU + 1];
__device__ int g_off_t2d[ND + 1];
__device__ int g_cur_t2u[NU];
__device__ int g_cur_t2d[ND];
__device__ int g_ss_t2u[EDG];
__device__ int g_ss_t2d[EDG];
__device__ int g_part_u[BU];
__device__ int g_part_d[BD];
__device__ uint4 g_wh_t2u_h[(size_t)NT * 8];   // fp16 rows (64 halves = 8 uint4)
__device__ uint4 g_wh_t2d_h[(size_t)NT * 8];
__device__ float2 g_p_u[NU];
__device__ float2 g_p_d[ND];
__device__ float g_w1c[2][128];   // [rel][c*2+o] : W1[{0,2}] @ Wc
__device__ float g_b1c[2][2];     // [rel][o]     : b1[{0,2}] @ Wc

// ---------------- zero the degree counters ----------------
__global__ void k_zero() {
    int i = blockIdx.x * blockDim.x + threadIdx.x;
    if (i < NT) { g_cnt_u2t[i] = 0; g_cnt_d2t[i] = 0; }
    if (i < NU) g_cnt_t2u[i] = 0;
    if (i < ND) g_cnt_t2d[i] = 0;
}

// ---------------- fused degree histogram over all 4 relations ----------------
__global__ void k_hist4(const int* __restrict__ d0, const int* __restrict__ d1,
                        const int* __restrict__ d2, const int* __restrict__ d3) {
    int i = blockIdx.x * blockDim.x + threadIdx.x;
    if (i < EDG)               atomicAdd(&g_cnt_u2t[d0[i]], 1);
    else if (i < 2 * EDG)      atomicAdd(&g_cnt_d2t[d1[i - EDG]], 1);
    else if (i < 3 * EDG)      atomicAdd(&g_cnt_t2u[d2[i - 2 * EDG]], 1);
    else if (i < 4 * EDG)      atomicAdd(&g_cnt_t2d[d3[i - 3 * EDG]], 1);
}

// ---------------- block-wide inclusive scan helper (<=32 warps) ----------------
__device__ __forceinline__ int block_scan_incl(int v) {
    __shared__ int wsum[32];
    int tid = threadIdx.x, lane = tid & 31, wid = tid >> 5;
    __syncthreads();   // protect wsum reuse across calls
    int x = v;
    #pragma unroll
    for (int d = 1; d < 32; d <<= 1) {
        int t = __shfl_up_sync(0xffffffffu, x, d);
        if (lane >= d) x += t;
    }
    if (lane == 31) wsum[wid] = x;
    __syncthreads();
    if (wid == 0) {
        int nW = (blockDim.x + 31) >> 5;
        int w = (lane < nW) ? wsum[lane] : 0;
        #pragma unroll
        for (int d = 1; d < 32; d <<= 1) {
            int t = __shfl_up_sync(0xffffffffu, w, d);
            if (lane >= d) w += t;
        }
        wsum[lane] = w;
    }
    __syncthreads();
    return x + (wid > 0 ? wsum[wid - 1] : 0);
}

// ---------------- scan phase 1: per-block exclusive scan + block totals ----------------
__global__ void k_scan_part() {
    int b = blockIdx.x;
    const int* cnt; int* off; int* part; int n; int lb;
    if (b < BU) { cnt = g_cnt_t2u; off = g_off_t2u; part = g_part_u; n = NU; lb = b; }
    else        { cnt = g_cnt_t2d; off = g_off_t2d; part = g_part_d; n = ND; lb = b - BU; }
    int i = lb * 1024 + threadIdx.x;
    int v = (i < n) ? cnt[i] : 0;
    int incl = block_scan_incl(v);
    if (i < n) off[i] = incl - v;
    if (threadIdx.x == 1023) part[lb] = incl;
}

// ---------------- scan phase 2: scan the block totals (one block, both rels) ----------------
__global__ void k_scan_tot() {
    int tid = threadIdx.x;   // 512 threads
    {
        int v = (tid < BU) ? g_part_u[tid] : 0;
        int incl = block_scan_incl(v);
        if (tid < BU) g_part_u[tid] = incl - v;
        if (tid == BU - 1) g_off_t2u[NU] = incl;
    }
    {
        int v = (tid < BD) ? g_part_d[tid] : 0;
        int incl = block_scan_incl(v);
        if (tid < BD) g_part_d[tid] = incl - v;
        if (tid == BD - 1) g_off_t2d[ND] = incl;
    }
}

// ---------------- scan phase 3: add block offsets, init cursors ----------------
__global__ void k_scan_add() {
    int b = blockIdx.x;
    int* off; int* cur; const int* part; int n; int lb;
    if (b < BU) { off = g_off_t2u; cur = g_cur_t2u; part = g_part_u; n = NU; lb = b; }
    else        { off = g_off_t2d; cur = g_cur_t2d; part = g_part_d; n = ND; lb = b - BU; }
    int i = lb * 1024 + threadIdx.x;
    if (i < n) {
        int o = off[i] + part[lb];
        off[i] = o;
        cur[i] = o;
    }
}

// ---------------- CSR fill for the two live relations ----------------
__global__ void k_fill2(const int* __restrict__ s2, const int* __restrict__ d2,
                        const int* __restrict__ s3, const int* __restrict__ d3) {
    int i = blockIdx.x * blockDim.x + threadIdx.x;
    if (i < EDG) {
        int p = atomicAdd(&g_cur_t2u[d2[i]], 1);
        g_ss_t2u[p] = s2[i];
    } else {
        int e = i - EDG;
        int p = atomicAdd(&g_cur_t2d[d3[e]], 1);
        g_ss_t2d[p] = s3[e];
    }
}

// ---------------- fold classifier into layer-1 weights: W1c = W1[rel]@Wc ----------------
__global__ void k_foldw(const float* __restrict__ W1, const float* __restrict__ b1,
                        const float* __restrict__ Wc) {
    int t = threadIdx.x;             // 256 threads
    int rel = t >> 7;                // 0 -> W1[0] (u path), 1 -> W1[2] (d path)
    int idx = t & 127;
    int c = idx >> 1, o = idx & 1;
    const float* Wsrc = W1 + (rel == 0 ? 0 : 2) * 4096;
    float s = 0.f;
    #pragma unroll 8
    for (int k = 0; k < 64; k++) s += Wsrc[c * 64 + k] * Wc[k * 2 + o];
    g_w1c[rel][idx] = s;
    if (t < 4) {
        int r2 = t >> 1, o2 = t & 1;
        const float* bsrc = b1 + (r2 == 0 ? 0 : 2) * 64;
        float sb = 0.f;
        #pragma unroll 8
        for (int k = 0; k < 64; k++) sb += bsrc[k] * Wc[k * 2 + o2];
        g_b1c[r2][o2] = sb;
    }
}

// ------- fused dual GEMM: wh_u = H@Wu+bu, wh_d = H@Wd+bd, fp16 outputs -------
__global__ __launch_bounds__(256) void k_gemm2(const float* __restrict__ H,
                                               const float* __restrict__ W0_,
                                               const float* __restrict__ b0_, int n) {
    __shared__ __align__(16) float Wu[64 * 64];
    __shared__ __align__(16) float Wd[64 * 64];
    __shared__ float As[64 * 65];
    int tid = threadIdx.x;

    const float4* Wu4 = (const float4*)(W0_ + 1 * 4096);
    const float4* Wd4 = (const float4*)(W0_ + 3 * 4096);
    float4* su = (float4*)Wu;
    float4* sd = (float4*)Wd;
    #pragma unroll
    for (int q = 0; q < 4; q++) { su[tid + q * 256] = Wu4[tid + q * 256];
                                  sd[tid + q * 256] = Wd4[tid + q * 256]; }

    int row0 = blockIdx.x * 64;
    const float4* H4 = (const float4*)H;
    #pragma unroll
    for (int q = 0; q < 4; q++) {
        int fidx = tid + q * 256;
        int r = fidx >> 4, c4 = fidx & 15;
        int gr = row0 + r;
        float4 v = make_float4(0.f, 0.f, 0.f, 0.f);
        if (gr < n) v = H4[(long)gr * 16 + c4];
        float* a = &As[r * 65 + c4 * 4];
        a[0] = v.x; a[1] = v.y; a[2] = v.z; a[3] = v.w;
    }
    __syncthreads();

    int r = tid >> 2, cg = tid & 3;
    float au[16], ad[16];
    #pragma unroll
    for (int j = 0; j < 16; j++) { au[j] = __ldg(&b0_[64 + cg * 16 + j]);
                                   ad[j] = __ldg(&b0_[192 + cg * 16 + j]); }

    const float* ap = &As[r * 65];
    #pragma unroll
    for (int k = 0; k < 64; k++) {
        float a = ap[k];
        const float4* wu = (const float4*)&Wu[k * 64 + cg * 16];
        const float4* wd = (const float4*)&Wd[k * 64 + cg * 16];
        #pragma unroll
        for (int q = 0; q < 4; q++) {
            float4 u = wu[q];
            au[q * 4 + 0] += a * u.x; au[q * 4 + 1] += a * u.y;
            au[q * 4 + 2] += a * u.z; au[q * 4 + 3] += a * u.w;
            float4 dd = wd[q];
            ad[q * 4 + 0] += a * dd.x; ad[q * 4 + 1] += a * dd.y;
            ad[q * 4 + 2] += a * dd.z; ad[q * 4 + 3] += a * dd.w;
        }
    }

    int gr = row0 + r;
    if (gr < n) {
        __half2 hu[8], hd[8];
        #pragma unroll
        for (int j = 0; j < 8; j++) {
            hu[j] = __floats2half2_rn(au[2 * j], au[2 * j + 1]);
            hd[j] = __floats2half2_rn(ad[2 * j], ad[2 * j + 1]);
        }
        uint4* ou = &g_wh_t2u_h[(long)gr * 8 + cg * 2];
        uint4* od = &g_wh_t2d_h[(long)gr * 8 + cg * 2];
        ou[0] = ((const uint4*)hu)[0];
        ou[1] = ((const uint4*)hu)[1];
        od[0] = ((const uint4*)hd)[0];
        od[1] = ((const uint4*)hd)[1];
    }
}

// ---- fused: fp16 mean-gather 64-dim -> leaky -> @W1c (64x2) + b1c -> p (n x 2) ----
// 8 threads per node, each owning 8 half features (one uint4 = 16B); unroll-4 for MLP.
__global__ __launch_bounds__(256) void k_gather_proj(const uint4* __restrict__ wh,
                                                     const int* __restrict__ off,
                                                     const int* __restrict__ ss,
                                                     int rel,
                                                     float2* __restrict__ p) {
    __shared__ float sw[128];
    __shared__ float sb[2];
    if (threadIdx.x < 128) sw[threadIdx.x] = g_w1c[rel][threadIdx.x];
    if (threadIdx.x < 2)   sb[threadIdx.x] = g_b1c[rel][threadIdx.x];
    __syncthreads();

    int t = blockIdx.x * blockDim.x + threadIdx.x;
    int node = t >> 3, j = t & 7;   // grids sized exactly: n*8 % 256 == 0

    int s0 = off[node], e0 = off[node + 1];
    float acc[8];
    #pragma unroll
    for (int q = 0; q < 8; q++) acc[q] = 0.f;

    int k = s0;
    for (; k + 4 <= e0; k += 4) {
        int i0 = __ldg(&ss[k]);
        int i1 = __ldg(&ss[k + 1]);
        int i2 = __ldg(&ss[k + 2]);
        int i3 = __ldg(&ss[k + 3]);
        uint4 q0 = __ldg(&wh[(long)i0 * 8 + j]);
        uint4 q1 = __ldg(&wh[(long)i1 * 8 + j]);
        uint4 q2 = __ldg(&wh[(long)i2 * 8 + j]);
        uint4 q3 = __ldg(&wh[(long)i3 * 8 + j]);
        const uint4 qs[4] = {q0, q1, q2, q3};
        #pragma unroll
        for (int u = 0; u < 4; u++) {
            const __half2* h = (const __half2*)&qs[u];
            #pragma unroll
            for (int w = 0; w < 4; w++) {
                float2 f = __half22float2(h[w]);
                acc[w * 2 + 0] += f.x;
                acc[w * 2 + 1] += f.y;
            }
        }
    }
    for (; k < e0; k++) {
        int s = __ldg(&ss[k]);
        uint4 q = __ldg(&wh[(long)s * 8 + j]);
        const __half2* h = (const __half2*)&q;
        #pragma unroll
        for (int w = 0; w < 4; w++) {
            float2 f = __half22float2(h[w]);
            acc[w * 2 + 0] += f.x;
            acc[w * 2 + 1] += f.y;
        }
    }

    int d = e0 - s0;
    float inv = 1.0f / (float)(d > 0 ? d : 1);
    float p0 = 0.f, p1 = 0.f;
    int c0 = j * 8;
    #pragma unroll
    for (int q = 0; q < 8; q++) {
        float m = acc[q] * inv;
        m = m > 0.f ? m : 0.01f * m;           // leaky relu
        p0 += m * sw[(c0 + q) * 2];
        p1 += m * sw[(c0 + q) * 2 + 1];
    }
    #pragma unroll
    for (int o = 4; o > 0; o >>= 1) {
        p0 += __shfl_down_sync(0xffffffffu, p0, o, 8);
        p1 += __shfl_down_sync(0xffffffffu, p1, o, 8);
    }
    if (j == 0) p[node] = make_float2(p0 + sb[0], p1 + sb[1]);
}

// ---------------- init output with bias ----------------
__global__ void k_out_init(const float* __restrict__ bc, float* __restrict__ out) {
    int i = blockIdx.x * blockDim.x + threadIdx.x;
    if (i < 2 * NT) out[i] = __ldg(&bc[i & 1]);
}

// -------- final: edge-parallel scatter of mean contributions into out --------
__global__ void k_scatter(const int* __restrict__ su, const int* __restrict__ du,
                          const int* __restrict__ sd, const int* __restrict__ dd,
                          float* __restrict__ out) {
    int i = blockIdx.x * blockDim.x + threadIdx.x;
    if (i < EDG) {
        int s = __ldg(&su[i]), d = __ldg(&du[i]);
        float2 v = *(const float2*)&g_p_u[s];
        int c = g_cnt_u2t[d];
        float inv = 1.0f / (float)(c > 0 ? c : 1);
        atomicAdd(&out[(long)d * 2 + 0], v.x * inv);
        atomicAdd(&out[(long)d * 2 + 1], v.y * inv);
    } else {
        int e = i - EDG;
        int s = __ldg(&sd[e]), d = __ldg(&dd[e]);
        float2 v = *(const float2*)&g_p_d[s];
        int c = g_cnt_d2t[d];
        float inv = 1.0f / (float)(c > 0 ? c : 1);
        atomicAdd(&out[(long)d * 2 + 0], v.x * inv);
        atomicAdd(&out[(long)d * 2 + 1], v.y * inv);
    }
}

static void* symaddr(const void* sym) {
    void* p = nullptr;
    cudaGetSymbolAddress(&p, sym);
    return p;
}

extern "C" void kernel_launch(void* const* d_in, const int* in_sizes, int n_in,
                              void* d_out, int out_size) {
    const float* features = (const float*)d_in[0];
    const float* W0 = (const float*)d_in[3];
    const float* b0 = (const float*)d_in[4];
    const float* W1 = (const float*)d_in[5];
    const float* b1 = (const float*)d_in[6];
    const float* Wc = (const float*)d_in[7];
    const float* bc = (const float*)d_in[8];
    const int* src_u2t = (const int*)d_in[9];
    const int* dst_u2t = (const int*)d_in[10];
    const int* src_t2u = (const int*)d_in[11];
    const int* dst_t2u = (const int*)d_in[12];
    const int* src_d2t = (const int*)d_in[13];
    const int* dst_d2t = (const int*)d_in[14];
    const int* src_t2d = (const int*)d_in[15];
    const int* dst_t2d = (const int*)d_in[16];
    float* out = (float*)d_out;

    int* off_t2u = (int*)symaddr(g_off_t2u);
    int* off_t2d = (int*)symaddr(g_off_t2d);
    int* ss_t2u  = (int*)symaddr(g_ss_t2u);
    int* ss_t2d  = (int*)symaddr(g_ss_t2d);
    uint4* wh_u  = (uint4*)symaddr(g_wh_t2u_h);
    uint4* wh_d  = (uint4*)symaddr(g_wh_t2d_h);
    float2* p_u  = (float2*)symaddr(g_p_u);
    float2* p_d  = (float2*)symaddr(g_p_d);

    const int TPB = 256;

    // ---- degree histogram (all 4 relations; u2t/d2t only need degrees) ----
    k_zero<<<(NT + TPB - 1) / TPB, TPB>>>();
    k_hist4<<<(4 * EDG) / TPB, TPB>>>(dst_u2t, dst_d2t, dst_t2u, dst_t2d);

    // ---- CSR offsets for the two live relations (3-phase parallel scan) ----
    k_scan_part<<<BU + BD, 1024>>>();
    k_scan_tot<<<1, 512>>>();
    k_scan_add<<<BU + BD, 1024>>>();
    k_fill2<<<(2 * EDG) / TPB, TPB>>>(src_t2u, dst_t2u, src_t2d, dst_t2d);

    // ---- fold classifier into layer-1 weights ----
    k_foldw<<<1, 256>>>(W1, b1, Wc);

    // ---- layer 0: fused dual projection, fp16 outputs ----
    k_gemm2<<<(NT + 63) / 64, TPB>>>(features, W0, b0, NT);

    // ---- fused gather + leaky + 2-wide layer-1 projection ----
    k_gather_proj<<<NU * 8 / TPB, TPB>>>(wh_u, off_t2u, ss_t2u, 0, p_u);
    k_gather_proj<<<ND * 8 / TPB, TPB>>>(wh_d, off_t2d, ss_t2d, 1, p_d);

    // ---- final: out = bc, then edge-parallel scatter of both relation means ----
    k_out_init<<<(2 * NT + TPB - 1) / TPB, TPB>>>(bc, out);
    k_scatter<<<(2 * EDG) / TPB, TPB>>>(src_u2t, dst_u2t, src_d2t, dst_d2t, out);
}